// round 12
// baseline (speedup 1.0000x reference)
#include <cuda_runtime.h>
#include <cuda_fp16.h>
#include <stdint.h>

#define NUM_EXPERTS 8
#define HIDDEN 2048
#define INTER 1408
#define NTOK 8192

#define BM 128
#define GT 128             // gemm block threads (4 warps)
#define THREADS 256        // router/gather threads
#define MAX_MTILES (NTOK/BM + NUM_EXPERTS - 1)   // 71
#define NB1 (INTER/64)     // 22
#define NB2 (HIDDEN/128)   // 16
#define NK1 (HIDDEN/32)    // 64
#define NK2 (INTER/32)     // 44
#define SA 40              // smem row stride (halfs)

#define STG (BM*SA)
#define STG_BYTES (STG*2)  // 10240
#define NSTAGE 4
#define SMEM_BYTES (2*NSTAGE*STG_BYTES)   // 81920 -> 2 CTAs/SM

#define TILE_GRID1 (MAX_MTILES*NB1)
#define CVTB 512           // tail blocks of gemm1 converting w2

// -------- device scratch --------
__device__ int g_offsets[NUM_EXPERTS + 1];
__device__ int g_mtoff[NUM_EXPERTS + 1];
__device__ int g_perm[NTOK];
__device__ __half g_w1[(size_t)NUM_EXPERTS * 2 * INTER * HIDDEN];
__device__ __half g_w2[(size_t)NUM_EXPERTS * HIDDEN * INTER];
__device__ __half g_x[(size_t)NTOK * HIDDEN];
__device__ __half g_h[(size_t)NTOK * INTER];

// -------- helpers --------
__device__ __forceinline__ uint32_t cvta_s(const void* p) {
    return (uint32_t)__cvta_generic_to_shared(p);
}
__device__ __forceinline__ void ldsm4(uint32_t& r0, uint32_t& r1,
                                      uint32_t& r2, uint32_t& r3, uint32_t addr) {
    asm volatile("ldmatrix.sync.aligned.m8n8.x4.shared.b16 {%0,%1,%2,%3},[%4];"
                 : "=r"(r0), "=r"(r1), "=r"(r2), "=r"(r3) : "r"(addr));
}
__device__ __forceinline__ void mma_f16(float c[4], const uint32_t a[4],
                                        uint32_t b0, uint32_t b1) {
    asm volatile(
        "mma.sync.aligned.m16n8k16.row.col.f32.f16.f16.f32 "
        "{%0,%1,%2,%3},{%4,%5,%6,%7},{%8,%9},{%0,%1,%2,%3};\n"
        : "+f"(c[0]), "+f"(c[1]), "+f"(c[2]), "+f"(c[3])
        : "r"(a[0]), "r"(a[1]), "r"(a[2]), "r"(a[3]), "r"(b0), "r"(b1));
}
__device__ __forceinline__ void cpa16(uint32_t s, const void* g) {
    asm volatile("cp.async.cg.shared.global [%0], [%1], 16;\n" :: "r"(s), "l"(g));
}
__device__ __forceinline__ void cp_commit() {
    asm volatile("cp.async.commit_group;\n" ::: "memory");
}
__device__ __forceinline__ void cp_wait2() {
    asm volatile("cp.async.wait_group 2;\n" ::: "memory");
}
__device__ __forceinline__ uint32_t pack2(float x, float y) {
    __half2 h = __floats2half2_rn(x, y);
    return *(uint32_t*)&h;
}
__device__ __forceinline__ uint4 pack8(float4 a, float4 b) {
    uint4 v;
    v.x = pack2(a.x, a.y); v.y = pack2(a.z, a.w);
    v.z = pack2(b.x, b.y); v.w = pack2(b.z, b.w);
    return v;
}

// -------- router --------
__global__ void k_router(const int* __restrict__ ids) {
    __shared__ int sc[NUM_EXPERTS];
    __shared__ int sb[NUM_EXPERTS];
    int t = threadIdx.x;
    if (t < NUM_EXPERTS) sc[t] = 0;
    __syncthreads();
    for (int i = t; i < NTOK; i += THREADS) atomicAdd(&sc[ids[i]], 1);
    __syncthreads();
    if (t == 0) {
        int off = 0, moff = 0;
        for (int e = 0; e < NUM_EXPERTS; e++) {
            g_offsets[e] = off; sb[e] = off; g_mtoff[e] = moff;
            off  += sc[e];
            moff += (sc[e] + BM - 1) / BM;
        }
        g_offsets[NUM_EXPERTS] = off;
        g_mtoff[NUM_EXPERTS]   = moff;
    }
    __syncthreads();
    if (t < NUM_EXPERTS) sc[t] = 0;
    __syncthreads();
    for (int i = t; i < NTOK; i += THREADS) {
        int e = ids[i];
        g_perm[sb[e] + atomicAdd(&sc[e], 1)] = i;
    }
}

// -------- pre-convert w1 only --------
__global__ void k_cvt1(const float* __restrict__ w1) {
    const long n16 = (long)NUM_EXPERTS * 2 * INTER * HIDDEN / 16;
    long stride = (long)gridDim.x * blockDim.x;
    for (long i = (long)blockIdx.x * blockDim.x + threadIdx.x; i < n16; i += stride) {
        const float4* s = (const float4*)w1 + 4 * i;
        float4 a = s[0], b = s[1], c = s[2], d = s[3];
        uint4* o = (uint4*)g_w1 + 2 * i;
        o[0] = pack8(a, b);
        o[1] = pack8(c, d);
    }
}

// -------- gather permuted fp16 tokens --------
__global__ void k_gather(const float* __restrict__ tokens) {
    const int s = blockIdx.x;
    const int tok = g_perm[s];
    const float4* src = (const float4*)(tokens + (size_t)tok * HIDDEN);
    uint4* dst = (uint4*)(g_x + (size_t)s * HIDDEN);
    for (int i = threadIdx.x; i < HIDDEN / 8; i += THREADS)
        dst[i] = pack8(src[2 * i], src[2 * i + 1]);
}

__device__ __forceinline__ bool decode_tile(int bx, int NB,
        int& e, int& nt, int& m_start, int& valid) {
    int total = g_mtoff[NUM_EXPERTS] * NB;
    if (bx >= total) return false;
    e = 0;
    while (bx >= g_mtoff[e + 1] * NB) e++;
    int local = bx - g_mtoff[e] * NB;
    int mt = g_mtoff[e + 1] - g_mtoff[e];
    nt = local / mt;
    int ml = local % mt;
    m_start = g_offsets[e] + ml * BM;
    valid = g_offsets[e + 1] - m_start;
    if (valid > BM) valid = BM;
    return true;
}

// ================= GEMM1: 4 warps, warp tile 64m x (32 gate + 32 up) =================
__global__ void __launch_bounds__(GT)
k_gemm1(const float* __restrict__ wts, const float* __restrict__ w2src) {
    extern __shared__ __half sm[];

    // tail blocks: convert w2 while tile blocks compute
    if (blockIdx.x >= TILE_GRID1) {
        const long n16 = (long)NUM_EXPERTS * HIDDEN * INTER / 16;
        const long base = (long)(blockIdx.x - TILE_GRID1) * GT + threadIdx.x;
        const long stride = (long)CVTB * GT;
        for (long i = base; i < n16; i += stride) {
            const float4* s = (const float4*)w2src + 4 * i;
            float4 a = s[0], b = s[1], c = s[2], d = s[3];
            uint4* o = (uint4*)g_w2 + 2 * i;
            o[0] = pack8(a, b);
            o[1] = pack8(c, d);
        }
        return;
    }

    int e, nt, m_start, valid;
    if (!decode_tile(blockIdx.x, NB1, e, nt, m_start, valid)) return;

    const int tid = threadIdx.x;
    const int lane = tid & 31;
    const int wid = tid >> 5;       // 0..3
    const int wm = wid >> 1;        // 0..1 : 64 m-rows
    const int wn = wid & 1;         // 0..1 : 32 h-cols (gate+up)
    const int n0 = nt * 64;

    // loaders: 1 thread per row, full 32-half (64B) row
    const int arc = (tid < valid) ? tid : (valid - 1);
    const __half* aptr = g_x + (size_t)(m_start + arc) * HIDDEN;
    const int brow = (tid < 64) ? (n0 + tid) : (INTER + n0 + tid - 64);
    const __half* bptr = g_w1 + (size_t)e * 2 * INTER * HIDDEN + (size_t)brow * HIDDEN;

    const uint32_t smb = cvta_s(sm);
    const uint32_t sAst = smb + (tid * SA) * 2;
    const uint32_t sBst = smb + NSTAGE * STG_BYTES + (tid * SA) * 2;
    const uint32_t aBase = smb + ((wm * 64 + (lane & 15)) * SA + (lane >> 4) * 8) * 2;
    const uint32_t bBase = smb + NSTAGE * STG_BYTES +
        ((wn * 32 + ((lane >> 4) * 8) + (lane & 7)) * SA + ((lane >> 3) & 1) * 8) * 2;

    float accg[4][4][4] = {};
    float accu[4][4][4] = {};

    auto issue = [&](int kt) {
        if (kt < NK1) {
            const int st = kt & (NSTAGE - 1);
            const __half* a = aptr + kt * 32;
            const __half* b = bptr + kt * 32;
            const uint32_t as = sAst + st * STG_BYTES;
            const uint32_t bs = sBst + st * STG_BYTES;
            cpa16(as,      a);      cpa16(as + 16, a + 8);
            cpa16(as + 32, a + 16); cpa16(as + 48, a + 24);
            cpa16(bs,      b);      cpa16(bs + 16, b + 8);
            cpa16(bs + 32, b + 16); cpa16(bs + 48, b + 24);
        }
        cp_commit();
    };

    issue(0); issue(1); issue(2);

    for (int kt = 0; kt < NK1; kt++) {
        cp_wait2();
        __syncthreads();
        issue(kt + 3);

        const int st = kt & (NSTAGE - 1);
        const uint32_t aS = aBase + st * STG_BYTES;
        const uint32_t bS = bBase + st * STG_BYTES;
#pragma unroll
        for (int ks = 0; ks < 2; ks++) {
            uint32_t a[4][4];
#pragma unroll
            for (int im = 0; im < 4; im++)
                ldsm4(a[im][0], a[im][1], a[im][2], a[im][3],
                      aS + ((im * 16 * SA + ks * 16) << 1));
#pragma unroll
            for (int jp = 0; jp < 2; jp++) {
                uint32_t g0, g1, g2, g3, u0, u1, u2, u3;
                ldsm4(g0, g1, g2, g3, bS + ((jp * 16 * SA + ks * 16) << 1));
                ldsm4(u0, u1, u2, u3, bS + (((64 + jp * 16) * SA + ks * 16) << 1));
#pragma unroll
                for (int im = 0; im < 4; im++) {
                    mma_f16(accg[im][jp * 2],     a[im], g0, g1);
                    mma_f16(accg[im][jp * 2 + 1], a[im], g2, g3);
                    mma_f16(accu[im][jp * 2],     a[im], u0, u1);
                    mma_f16(accu[im][jp * 2 + 1], a[im], u2, u3);
                }
            }
        }
    }

    // epilogue: silu(g)*u*wt -> g_h (fp16)
#pragma unroll
    for (int im = 0; im < 4; im++) {
#pragma unroll
        for (int half = 0; half < 2; half++) {
            const int r = wm * 64 + im * 16 + half * 8 + (lane >> 2);
            if (r < valid) {
                const int s = m_start + r;
                const float wt = wts[g_perm[s]];
                __half* dst = g_h + (size_t)s * INTER + n0 + wn * 32 + (lane & 3) * 2;
#pragma unroll
                for (int jn = 0; jn < 4; jn++) {
                    float gx = accg[im][jn][half * 2 + 0];
                    float gy = accg[im][jn][half * 2 + 1];
                    float ux = accu[im][jn][half * 2 + 0];
                    float uy = accu[im][jn][half * 2 + 1];
                    float hx = (gx / (1.0f + __expf(-gx))) * ux * wt;
                    float hy = (gy / (1.0f + __expf(-gy))) * uy * wt;
                    *(__half2*)(dst + jn * 8) = __floats2half2_rn(hx, hy);
                }
            }
        }
    }
}

// ================= GEMM2: 4 warps, warp tile 64m x 64n =================
__global__ void __launch_bounds__(GT)
k_gemm2(float* __restrict__ out) {
    extern __shared__ __half sm[];

    int e, nt, m_start, valid;
    if (!decode_tile(blockIdx.x, NB2, e, nt, m_start, valid)) return;

    const int tid = threadIdx.x;
    const int lane = tid & 31;
    const int wid = tid >> 5;
    const int wm = wid >> 1;
    const int wn = wid & 1;
    const int n0 = nt * 128;

    const int arc = (tid < valid) ? tid : (valid - 1);
    const __half* aptr = g_h + (size_t)(m_start + arc) * INTER;
    const __half* bptr = g_w2 + (size_t)e * HIDDEN * INTER + (size_t)(n0 + tid) * INTER;

    const uint32_t smb = cvta_s(sm);
    const uint32_t sAst = smb + (tid * SA) * 2;
    const uint32_t sBst = smb + NSTAGE * STG_BYTES + (tid * SA) * 2;
    const uint32_t aBase = smb + ((wm * 64 + (lane & 15)) * SA + (lane >> 4) * 8) * 2;
    const uint32_t bBase = smb + NSTAGE * STG_BYTES +
        ((wn * 64 + ((lane >> 4) * 8) + (lane & 7)) * SA + ((lane >> 3) & 1) * 8) * 2;

    float acc[4][8][4] = {};

    auto issue = [&](int kt) {
        if (kt < NK2) {
            const int st = kt & (NSTAGE - 1);
            const __half* a = aptr + kt * 32;
            const __half* b = bptr + kt * 32;
            const uint32_t as = sAst + st * STG_BYTES;
            const uint32_t bs = sBst + st * STG_BYTES;
            cpa16(as,      a);      cpa16(as + 16, a + 8);
            cpa16(as + 32, a + 16); cpa16(as + 48, a + 24);
            cpa16(bs,      b);      cpa16(bs + 16, b + 8);
            cpa16(bs + 32, b + 16); cpa16(bs + 48, b + 24);
        }
        cp_commit();
    };

    issue(0); issue(1); issue(2);

    for (int kt = 0; kt < NK2; kt++) {
        cp_wait2();
        __syncthreads();
        issue(kt + 3);

        const int st = kt & (NSTAGE - 1);
        const uint32_t aS = aBase + st * STG_BYTES;
        const uint32_t bS = bBase + st * STG_BYTES;
#pragma unroll
        for (int ks = 0; ks < 2; ks++) {
            uint32_t a[4][4];
#pragma unroll
            for (int im = 0; im < 4; im++)
                ldsm4(a[im][0], a[im][1], a[im][2], a[im][3],
                      aS + ((im * 16 * SA + ks * 16) << 1));
#pragma unroll
            for (int jp = 0; jp < 4; jp++) {
                uint32_t b0, b1, b2, b3;
                ldsm4(b0, b1, b2, b3, bS + ((jp * 16 * SA + ks * 16) << 1));
#pragma unroll
                for (int im = 0; im < 4; im++) {
                    mma_f16(acc[im][jp * 2],     a[im], b0, b1);
                    mma_f16(acc[im][jp * 2 + 1], a[im], b2, b3);
                }
            }
        }
    }

#pragma unroll
    for (int im = 0; im < 4; im++) {
#pragma unroll
        for (int half = 0; half < 2; half++) {
            const int r = wm * 64 + im * 16 + half * 8 + (lane >> 2);
            if (r < valid) {
                const int tok = g_perm[m_start + r];
                float* dst = out + (size_t)tok * HIDDEN + n0 + wn * 64 + (lane & 3) * 2;
#pragma unroll
                for (int jn = 0; jn < 8; jn++) {
                    float2 v;
                    v.x = acc[im][jn][half * 2 + 0];
                    v.y = acc[im][jn][half * 2 + 1];
                    *(float2*)(dst + jn * 8) = v;
                }
            }
        }
    }
}

// -------- launch --------
extern "C" void kernel_launch(void* const* d_in, const int* in_sizes, int n_in,
                              void* d_out, int out_size) {
    const float* tokens = (const float*)d_in[0];
    const int*   ids    = (const int*)d_in[1];
    const float* wts    = (const float*)d_in[2];
    const float* gu     = (const float*)d_in[3];
    const float* down   = (const float*)d_in[4];
    float* out = (float*)d_out;

    cudaFuncSetAttribute(k_gemm1, cudaFuncAttributeMaxDynamicSharedMemorySize, SMEM_BYTES);
    cudaFuncSetAttribute(k_gemm2, cudaFuncAttributeMaxDynamicSharedMemorySize, SMEM_BYTES);

    k_router<<<1, THREADS>>>(ids);
    k_cvt1<<<148 * 16, 256>>>(gu);
    k_gather<<<NTOK, THREADS>>>(tokens);

    k_gemm1<<<TILE_GRID1 + CVTB, GT, SMEM_BYTES>>>(wts, down);
    k_gemm2<<<MAX_MTILES * NB2, GT, SMEM_BYTES>>>(out);
}

// round 13
// speedup vs baseline: 1.3520x; 1.3520x over previous
#include <cuda_runtime.h>
#include <cuda_fp16.h>
#include <stdint.h>

#define NUM_EXPERTS 8
#define HIDDEN 2048
#define INTER 1408
#define NTOK 8192

#define BM 128
#define THREADS 256
#define MAX_MTILES (NTOK/BM + NUM_EXPERTS - 1)   // 71
#define NB1 (INTER/64)     // 22
#define NB2 (HIDDEN/128)   // 16
#define NK1 (HIDDEN/32)    // 64
#define NK2 (INTER/32)     // 44
#define SA 40              // smem row stride (halfs), conflict-free ldsm

#define STG (BM*SA)
#define STG_BYTES (STG*2)
#define NSTAGE 4
#define SMEM_BYTES (2*NSTAGE*STG_BYTES)   // 81920

#define TILE_GRID1 (MAX_MTILES*NB1)
#define CVTB 512            // tail blocks of gemm1 that convert w2

// -------- device scratch --------
__device__ int g_offsets[NUM_EXPERTS + 1];
__device__ int g_mtoff[NUM_EXPERTS + 1];
__device__ int g_perm[NTOK];
__device__ __half g_w1[(size_t)NUM_EXPERTS * 2 * INTER * HIDDEN];
__device__ __half g_w2[(size_t)NUM_EXPERTS * HIDDEN * INTER];
__device__ __half g_x[(size_t)NTOK * HIDDEN];    // fp16 tokens, ORIGINAL order
__device__ __half g_h[(size_t)NTOK * INTER];

// -------- helpers --------
__device__ __forceinline__ uint32_t cvta_s(const void* p) {
    return (uint32_t)__cvta_generic_to_shared(p);
}
__device__ __forceinline__ void ldsm4(uint32_t& r0, uint32_t& r1,
                                      uint32_t& r2, uint32_t& r3, uint32_t addr) {
    asm volatile("ldmatrix.sync.aligned.m8n8.x4.shared.b16 {%0,%1,%2,%3},[%4];"
                 : "=r"(r0), "=r"(r1), "=r"(r2), "=r"(r3) : "r"(addr));
}
__device__ __forceinline__ void mma_f16(float c[4], const uint32_t a[4],
                                        uint32_t b0, uint32_t b1) {
    asm volatile(
        "mma.sync.aligned.m16n8k16.row.col.f32.f16.f16.f32 "
        "{%0,%1,%2,%3},{%4,%5,%6,%7},{%8,%9},{%0,%1,%2,%3};\n"
        : "+f"(c[0]), "+f"(c[1]), "+f"(c[2]), "+f"(c[3])
        : "r"(a[0]), "r"(a[1]), "r"(a[2]), "r"(a[3]), "r"(b0), "r"(b1));
}
__device__ __forceinline__ void cpa16(uint32_t s, const void* g) {
    asm volatile("cp.async.cg.shared.global [%0], [%1], 16;\n" :: "r"(s), "l"(g));
}
__device__ __forceinline__ void cp_commit() {
    asm volatile("cp.async.commit_group;\n" ::: "memory");
}
__device__ __forceinline__ void cp_wait2() {
    asm volatile("cp.async.wait_group 2;\n" ::: "memory");
}
__device__ __forceinline__ uint32_t pack2(float x, float y) {
    __half2 h = __floats2half2_rn(x, y);
    return *(uint32_t*)&h;
}
__device__ __forceinline__ uint4 pack8(float4 a, float4 b) {
    uint4 v;
    v.x = pack2(a.x, a.y); v.y = pack2(a.z, a.w);
    v.z = pack2(b.x, b.y); v.w = pack2(b.z, b.w);
    return v;
}

// -------- pre-pass: block 0 = router; other blocks convert w1 + tokens --------
__global__ void k_pre(const int* __restrict__ ids,
                      const float* __restrict__ w1,
                      const float* __restrict__ tokens) {
    if (blockIdx.x == 0) {
        __shared__ int sc[NUM_EXPERTS];
        __shared__ int sb[NUM_EXPERTS];
        int t = threadIdx.x;
        if (t < NUM_EXPERTS) sc[t] = 0;
        __syncthreads();
        for (int i = t; i < NTOK; i += THREADS) atomicAdd(&sc[ids[i]], 1);
        __syncthreads();
        if (t == 0) {
            int off = 0, moff = 0;
            for (int e = 0; e < NUM_EXPERTS; e++) {
                g_offsets[e] = off; sb[e] = off; g_mtoff[e] = moff;
                off  += sc[e];
                moff += (sc[e] + BM - 1) / BM;
            }
            g_offsets[NUM_EXPERTS] = off;
            g_mtoff[NUM_EXPERTS]   = moff;
        }
        __syncthreads();
        if (t < NUM_EXPERTS) sc[t] = 0;
        __syncthreads();
        for (int i = t; i < NTOK; i += THREADS) {
            int e = ids[i];
            g_perm[sb[e] + atomicAdd(&sc[e], 1)] = i;
        }
        return;
    }
    // conversion blocks: w1 then tokens, 16-element chunks
    const long c_w1 = (long)NUM_EXPERTS * 2 * INTER * HIDDEN / 16;
    const long c_x  = (long)NTOK * HIDDEN / 16;
    const long total = c_w1 + c_x;
    const long stride = (long)(gridDim.x - 1) * blockDim.x;
    for (long i = (long)(blockIdx.x - 1) * blockDim.x + threadIdx.x;
         i < total; i += stride) {
        const float* src; __half* dst; long j;
        if (i < c_w1) { src = w1;     dst = g_w1; j = i; }
        else          { src = tokens; dst = g_x;  j = i - c_w1; }
        const float4* s = (const float4*)src + 4 * j;
        float4 a = s[0], b = s[1], c = s[2], d = s[3];
        uint4* o = (uint4*)dst + 2 * j;
        o[0] = pack8(a, b);
        o[1] = pack8(c, d);
    }
}

__device__ __forceinline__ bool decode_tile(int bx, int NB,
        int& e, int& nt, int& m_start, int& valid) {
    int total = g_mtoff[NUM_EXPERTS] * NB;
    if (bx >= total) return false;
    e = 0;
    while (bx >= g_mtoff[e + 1] * NB) e++;
    int local = bx - g_mtoff[e] * NB;
    int mt = g_mtoff[e + 1] - g_mtoff[e];
    nt = local / mt;
    int ml = local % mt;
    m_start = g_offsets[e] + ml * BM;
    valid = g_offsets[e + 1] - m_start;
    if (valid > BM) valid = BM;
    return true;
}

// ================= GEMM1 (+ w2 conversion in tail blocks) =================
__global__ void __launch_bounds__(THREADS)
k_gemm1(const float* __restrict__ wts, const float* __restrict__ w2src) {
    extern __shared__ __half sm[];

    // tail blocks: convert w2 while the tile blocks compute
    if (blockIdx.x >= TILE_GRID1) {
        const long n16 = (long)NUM_EXPERTS * HIDDEN * INTER / 16;
        const long base = (long)(blockIdx.x - TILE_GRID1) * blockDim.x + threadIdx.x;
        const long stride = (long)CVTB * blockDim.x;
        for (long i = base; i < n16; i += stride) {
            const float4* s = (const float4*)w2src + 4 * i;
            float4 a = s[0], b = s[1], c = s[2], d = s[3];
            uint4* o = (uint4*)g_w2 + 2 * i;
            o[0] = pack8(a, b);
            o[1] = pack8(c, d);
        }
        return;
    }

    int e, nt, m_start, valid;
    if (!decode_tile(blockIdx.x, NB1, e, nt, m_start, valid)) return;

    const int tid = threadIdx.x;
    const int lane = tid & 31;
    const int wid = tid >> 5;
    const int wm = wid >> 1;
    const int wn = wid & 1;
    const int n0 = nt * 64;

    const int lr = tid >> 1;
    const int lc = (tid & 1) * 16;
    const int arc = (lr < valid) ? lr : (valid - 1);
    const int atok = g_perm[m_start + arc];
    const __half* aptr = g_x + (size_t)atok * HIDDEN + lc;
    const int brow = (lr < 64) ? (n0 + lr) : (INTER + n0 + lr - 64);
    const __half* bptr = g_w1 + (size_t)e * 2 * INTER * HIDDEN + (size_t)brow * HIDDEN + lc;

    const uint32_t smb = cvta_s(sm);
    const uint32_t sAst = smb + (lr * SA + lc) * 2;
    const uint32_t sBst = smb + NSTAGE * STG_BYTES + (lr * SA + lc) * 2;
    const uint32_t aBase = smb + ((wm * 32 + (lane & 15)) * SA + (lane >> 4) * 8) * 2;
    const uint32_t bBase = smb + NSTAGE * STG_BYTES +
        ((wn * 32 + ((lane >> 4) * 8) + (lane & 7)) * SA + ((lane >> 3) & 1) * 8) * 2;

    float accg[2][4][4] = {};
    float accu[2][4][4] = {};

    auto issue = [&](int kt) {
        if (kt < NK1) {
            const int st = kt & (NSTAGE - 1);
            const __half* a = aptr + kt * 32;
            const __half* b = bptr + kt * 32;
            cpa16(sAst + st * STG_BYTES,      a);
            cpa16(sAst + st * STG_BYTES + 16, a + 8);
            cpa16(sBst + st * STG_BYTES,      b);
            cpa16(sBst + st * STG_BYTES + 16, b + 8);
        }
        cp_commit();
    };

    issue(0); issue(1); issue(2);

    for (int kt = 0; kt < NK1; kt++) {
        cp_wait2();
        __syncthreads();
        issue(kt + 3);

        const int st = kt & (NSTAGE - 1);
        const uint32_t aS = aBase + st * STG_BYTES;
        const uint32_t bS = bBase + st * STG_BYTES;
#pragma unroll
        for (int ks = 0; ks < 2; ks++) {
            uint32_t a[2][4];
#pragma unroll
            for (int im = 0; im < 2; im++)
                ldsm4(a[im][0], a[im][1], a[im][2], a[im][3],
                      aS + ((im * 16 * SA + ks * 16) << 1));
#pragma unroll
            for (int jp = 0; jp < 2; jp++) {
                uint32_t g0, g1, g2, g3, u0, u1, u2, u3;
                ldsm4(g0, g1, g2, g3, bS + ((jp * 16 * SA + ks * 16) << 1));
                ldsm4(u0, u1, u2, u3, bS + (((64 + jp * 16) * SA + ks * 16) << 1));
#pragma unroll
                for (int im = 0; im < 2; im++) {
                    mma_f16(accg[im][jp * 2],     a[im], g0, g1);
                    mma_f16(accg[im][jp * 2 + 1], a[im], g2, g3);
                    mma_f16(accu[im][jp * 2],     a[im], u0, u1);
                    mma_f16(accu[im][jp * 2 + 1], a[im], u2, u3);
                }
            }
        }
    }

    // epilogue: silu(g)*u*wt -> g_h (fp16)
#pragma unroll
    for (int im = 0; im < 2; im++) {
#pragma unroll
        for (int half = 0; half < 2; half++) {
            const int r = wm * 32 + im * 16 + half * 8 + (lane >> 2);
            if (r < valid) {
                const int s = m_start + r;
                const float wt = wts[g_perm[s]];
                __half* dst = g_h + (size_t)s * INTER + n0 + wn * 32 + (lane & 3) * 2;
#pragma unroll
                for (int jn = 0; jn < 4; jn++) {
                    float gx = accg[im][jn][half * 2 + 0];
                    float gy = accg[im][jn][half * 2 + 1];
                    float ux = accu[im][jn][half * 2 + 0];
                    float uy = accu[im][jn][half * 2 + 1];
                    float hx = (gx / (1.0f + __expf(-gx))) * ux * wt;
                    float hy = (gy / (1.0f + __expf(-gy))) * uy * wt;
                    *(__half2*)(dst + jn * 8) = __floats2half2_rn(hx, hy);
                }
            }
        }
    }
}

// ================= GEMM2 (BN=128) =================
__global__ void __launch_bounds__(THREADS)
k_gemm2(float* __restrict__ out) {
    extern __shared__ __half sm[];

    int e, nt, m_start, valid;
    if (!decode_tile(blockIdx.x, NB2, e, nt, m_start, valid)) return;

    const int tid = threadIdx.x;
    const int lane = tid & 31;
    const int wid = tid >> 5;
    const int wm = wid >> 1;
    const int wn = wid & 1;
    const int n0 = nt * 128;

    const int lr = tid >> 1;
    const int lc = (tid & 1) * 16;
    const int arc = (lr < valid) ? lr : (valid - 1);
    const __half* aptr = g_h + (size_t)(m_start + arc) * INTER + lc;
    const __half* bptr = g_w2 + (size_t)e * HIDDEN * INTER + (size_t)(n0 + lr) * INTER + lc;

    const uint32_t smb = cvta_s(sm);
    const uint32_t sAst = smb + (lr * SA + lc) * 2;
    const uint32_t sBst = smb + NSTAGE * STG_BYTES + (lr * SA + lc) * 2;
    const uint32_t aBase = smb + ((wm * 32 + (lane & 15)) * SA + (lane >> 4) * 8) * 2;
    const uint32_t bBase = smb + NSTAGE * STG_BYTES +
        ((wn * 64 + ((lane >> 4) * 8) + (lane & 7)) * SA + ((lane >> 3) & 1) * 8) * 2;

    float acc[2][8][4] = {};

    auto issue = [&](int kt) {
        if (kt < NK2) {
            const int st = kt & (NSTAGE - 1);
            const __half* a = aptr + kt * 32;
            const __half* b = bptr + kt * 32;
            cpa16(sAst + st * STG_BYTES,      a);
            cpa16(sAst + st * STG_BYTES + 16, a + 8);
            cpa16(sBst + st * STG_BYTES,      b);
            cpa16(sBst + st * STG_BYTES + 16, b + 8);
        }
        cp_commit();
    };

    issue(0); issue(1); issue(2);

    for (int kt = 0; kt < NK2; kt++) {
        cp_wait2();
        __syncthreads();
        issue(kt + 3);

        const int st = kt & (NSTAGE - 1);
        const uint32_t aS = aBase + st * STG_BYTES;
        const uint32_t bS = bBase + st * STG_BYTES;
#pragma unroll
        for (int ks = 0; ks < 2; ks++) {
            uint32_t a[2][4];
#pragma unroll
            for (int im = 0; im < 2; im++)
                ldsm4(a[im][0], a[im][1], a[im][2], a[im][3],
                      aS + ((im * 16 * SA + ks * 16) << 1));
#pragma unroll
            for (int jp = 0; jp < 4; jp++) {
                uint32_t b0, b1, b2, b3;
                ldsm4(b0, b1, b2, b3, bS + ((jp * 16 * SA + ks * 16) << 1));
#pragma unroll
                for (int im = 0; im < 2; im++) {
                    mma_f16(acc[im][jp * 2],     a[im], b0, b1);
                    mma_f16(acc[im][jp * 2 + 1], a[im], b2, b3);
                }
            }
        }
    }

#pragma unroll
    for (int im = 0; im < 2; im++) {
#pragma unroll
        for (int half = 0; half < 2; half++) {
            const int r = wm * 32 + im * 16 + half * 8 + (lane >> 2);
            if (r < valid) {
                const int tok = g_perm[m_start + r];
                float* dst = out + (size_t)tok * HIDDEN + n0 + wn * 64 + (lane & 3) * 2;
#pragma unroll
                for (int jn = 0; jn < 8; jn++) {
                    float2 v;
                    v.x = acc[im][jn][half * 2 + 0];
                    v.y = acc[im][jn][half * 2 + 1];
                    *(float2*)(dst + jn * 8) = v;
                }
            }
        }
    }
}

// -------- launch --------
extern "C" void kernel_launch(void* const* d_in, const int* in_sizes, int n_in,
                              void* d_out, int out_size) {
    const float* tokens = (const float*)d_in[0];
    const int*   ids    = (const int*)d_in[1];
    const float* wts    = (const float*)d_in[2];
    const float* gu     = (const float*)d_in[3];
    const float* down   = (const float*)d_in[4];
    float* out = (float*)d_out;

    cudaFuncSetAttribute(k_gemm1, cudaFuncAttributeMaxDynamicSharedMemorySize, SMEM_BYTES);
    cudaFuncSetAttribute(k_gemm2, cudaFuncAttributeMaxDynamicSharedMemorySize, SMEM_BYTES);

    k_pre<<<148 * 16 + 1, THREADS>>>(ids, gu, tokens);

    k_gemm1<<<TILE_GRID1 + CVTB, THREADS, SMEM_BYTES>>>(wts, down);
    k_gemm2<<<MAX_MTILES * NB2, THREADS, SMEM_BYTES>>>(out);
}